// round 14
// baseline (speedup 1.0000x reference)
#include <cuda_runtime.h>
#include <cuda_bf16.h>
#include <math.h>

// ForwardBackwardImputer: out[b,t,:] = x[b, idx_fwd[b,t], :]
// mask[t] = all(|x[b,t,d]| <= 1e-6); idx_fwd = inclusive cummax(mask ? 0 : t).
// (Backward-fill branch of the reference is provably identical to x_fwd;
//  verified rel_err==0 across rounds.)
//
// Kernel A: mask + copy-through + IN-GROUP forward fill. A warp holds 4
//   consecutive rows in registers; any missing row with a valid predecessor
//   in its group is filled here for free. Only "unresolved" rows (all-missing
//   group prefix, ~2.8%) are left, flagged in g_mask.
// Kernel B: warp-local gather fill of unresolved rows. Sources are the
//   nearest RESOLVED row (gathered from `out`, which already holds its final
//   value) or zeros when no resolved predecessor exists (reference maps the
//   leading missing block to x[0] == zero row).

#define L_SEQ 2048
#define D_FEAT 128
#define ROW_F4 (D_FEAT / 4)   // 32 float4 per timestep row
#define ATOL_F 1e-6f

#define A_THREADS 256
#define A_WARPS   8
#define A_GRID    1024        // 8192 warps; 65536... see launch: 16 groups/warp exact

#define B_THREADS 256
#define B_WARPS   8
#define B_SLICES  4                      // CTAs per batch row
#define SLICE_LEN (L_SEQ / B_SLICES)     // 512 timesteps per CTA
#define WARP_SPAN 64                     // timesteps per warp in B

// Max problem we support: 1024 batch rows of 2048 steps.
// Byte semantics: 1 = UNRESOLVED after kernel A, 0 = resolved (out is final).
__device__ unsigned char g_mask[1024 * L_SEQ];   // 2 MB

// ---------------- Kernel A: mask + copy-through + in-group fill ------------
__global__ __launch_bounds__(A_THREADS, 8)
void mask_copy_kernel(const float4* __restrict__ x, float4* __restrict__ out,
                      int ngroups) {   // ngroups = (B*L)/4
    const int lane = threadIdx.x & 31;
    const int wid  = threadIdx.x >> 5;
    const unsigned FULL = 0xffffffffu;
    const int totalW = gridDim.x * A_WARPS;

    for (int g = blockIdx.x * A_WARPS + wid; g < ngroups; g += totalW) {
        const int r0 = g << 2;  // flattened (b*L + t) row base
        float4 v0 = x[(r0 + 0) * ROW_F4 + lane];
        float4 v1 = x[(r0 + 1) * ROW_F4 + lane];
        float4 v2 = x[(r0 + 2) * ROW_F4 + lane];
        float4 v3 = x[(r0 + 3) * ROW_F4 + lane];

        bool z0 = (fabsf(v0.x) <= ATOL_F) & (fabsf(v0.y) <= ATOL_F) &
                  (fabsf(v0.z) <= ATOL_F) & (fabsf(v0.w) <= ATOL_F);
        bool z1 = (fabsf(v1.x) <= ATOL_F) & (fabsf(v1.y) <= ATOL_F) &
                  (fabsf(v1.z) <= ATOL_F) & (fabsf(v1.w) <= ATOL_F);
        bool z2 = (fabsf(v2.x) <= ATOL_F) & (fabsf(v2.y) <= ATOL_F) &
                  (fabsf(v2.z) <= ATOL_F) & (fabsf(v2.w) <= ATOL_F);
        bool z3 = (fabsf(v3.x) <= ATOL_F) & (fabsf(v3.y) <= ATOL_F) &
                  (fabsf(v3.z) <= ATOL_F) & (fabsf(v3.w) <= ATOL_F);

        unsigned m0 = __all_sync(FULL, z0);
        unsigned m1 = __all_sync(FULL, z1);
        unsigned m2 = __all_sync(FULL, z2);
        unsigned m3 = __all_sync(FULL, z3);

        // Row 0: its own value if valid, else unresolved.
        if (!m0) __stcs(&out[(r0 + 0) * ROW_F4 + lane], v0);
        // Rows 1-3: own value, else nearest valid in-group predecessor.
        if (!m1)      __stcs(&out[(r0 + 1) * ROW_F4 + lane], v1);
        else if (!m0) __stcs(&out[(r0 + 1) * ROW_F4 + lane], v0);

        if (!m2)      __stcs(&out[(r0 + 2) * ROW_F4 + lane], v2);
        else if (!m1) __stcs(&out[(r0 + 2) * ROW_F4 + lane], v1);
        else if (!m0) __stcs(&out[(r0 + 2) * ROW_F4 + lane], v0);

        if (!m3)      __stcs(&out[(r0 + 3) * ROW_F4 + lane], v3);
        else if (!m2) __stcs(&out[(r0 + 3) * ROW_F4 + lane], v2);
        else if (!m1) __stcs(&out[(r0 + 3) * ROW_F4 + lane], v1);
        else if (!m0) __stcs(&out[(r0 + 3) * ROW_F4 + lane], v0);

        if (lane == 0) {
            // Unresolved = missing AND all-missing group prefix (cumulative AND).
            unsigned u0 = m0;
            unsigned u1 = u0 & m1;
            unsigned u2 = u1 & m2;
            unsigned u3 = u2 & m3;
            uchar4 mm = make_uchar4((unsigned char)u0, (unsigned char)u1,
                                    (unsigned char)u2, (unsigned char)u3);
            *reinterpret_cast<uchar4*>(&g_mask[r0]) = mm;
        }
    }
}

// ---------------- Kernel B: gather fill of unresolved rows -----------------
// grid = B * B_SLICES, 8 warps/CTA, 64 timesteps/warp. g_mask byte==1 means
// unresolved. Source = nearest resolved row (value read from `out`), or the
// zero row when no resolved predecessor exists (sentinel -1, store zeros).
__global__ __launch_bounds__(B_THREADS)
void fill_kernel(const float* __restrict__ x, float* __restrict__ out) {
    const int b     = blockIdx.x >> 2;           // B_SLICES == 4
    const int slice = blockIdx.x & 3;
    float4* __restrict__ ob =
        reinterpret_cast<float4*>(out + (size_t)b * L_SEQ * D_FEAT);

    __shared__ short s_list[B_WARPS][WARP_SPAN];
    __shared__ short s_src [B_WARPS][WARP_SPAN];

    const int lane = threadIdx.x & 31;
    const int wid  = threadIdx.x >> 5;
    const unsigned FULL = 0xffffffffu;
    const unsigned lt = (1u << lane) - 1u;

    const int s0 = slice * SLICE_LEN + wid * WARP_SPAN;   // span start (in row)
    const int gbase = b * L_SEQ;

    // Span mask bytes + speculative carry chunk (overlap the 3 loads).
    unsigned char m0 = g_mask[gbase + s0 + lane];
    unsigned char m1 = g_mask[gbase + s0 + 32 + lane];
    unsigned char mc = (s0 >= 32) ? g_mask[gbase + s0 - 32 + lane]
                                  : (unsigned char)1;

    unsigned miss0 = __ballot_sync(FULL, m0 != 0);
    unsigned miss1 = __ballot_sync(FULL, m1 != 0);
    if ((miss0 | miss1) == 0u) return;          // warp-uniform early exit

    const unsigned res0 = ~miss0;   // resolved within span (out is final)
    const unsigned res1 = ~miss1;

    // Carry-in: nearest resolved index before s0. Sentinel -1 = none ->
    // reference output is the zero row.
    int carry = -1;
    {
        unsigned vb = (s0 >= 32) ? ~__ballot_sync(FULL, mc != 0) : 0u;
        if (vb) {
            carry = (s0 - 32) + (31 - __clz(vb));
        } else {
            for (int off = s0 - 64; off >= 0; off -= 32) {
                unsigned char mb = g_mask[gbase + off + lane];
                unsigned vb2 = ~__ballot_sync(FULL, mb != 0);
                if (vb2) { carry = off + (31 - __clz(vb2)); break; }
            }
        }
    }

    // Per-lane source index for its own timestep (if unresolved).
    unsigned rb0 = res0 & lt;
    int src0 = rb0 ? (s0 + (31 - __clz(rb0))) : carry;

    unsigned rb1 = res1 & lt;
    int src1;
    if (rb1)       src1 = s0 + 32 + (31 - __clz(rb1));
    else if (res0) src1 = s0 + (31 - __clz(res0));
    else           src1 = carry;

    // Ballot-compact (t, src) pairs into smem work lists.
    const int c0  = __popc(miss0);
    const int cnt = c0 + __popc(miss1);
    if (m0) {
        int p = __popc(miss0 & lt);
        s_list[wid][p] = (short)(s0 + lane);
        s_src [wid][p] = (short)src0;
    }
    if (m1) {
        int p = c0 + __popc(miss1 & lt);
        s_list[wid][p] = (short)(s0 + 32 + lane);
        s_src [wid][p] = (short)src1;
    }
    __syncwarp();

    const float4 zero = make_float4(0.f, 0.f, 0.f, 0.f);

    // Fill: gather from OUT (resolved rows hold final values), 4 in flight.
    int i = 0;
    for (; i + 4 <= cnt; i += 4) {
        int ta = (int)s_list[wid][i + 0];
        int tb = (int)s_list[wid][i + 1];
        int tc = (int)s_list[wid][i + 2];
        int td = (int)s_list[wid][i + 3];
        int sa = (int)s_src[wid][i + 0];
        int sb = (int)s_src[wid][i + 1];
        int sc = (int)s_src[wid][i + 2];
        int sd = (int)s_src[wid][i + 3];
        float4 va = (sa >= 0) ? ob[sa * ROW_F4 + lane] : zero;
        float4 vb = (sb >= 0) ? ob[sb * ROW_F4 + lane] : zero;
        float4 vc = (sc >= 0) ? ob[sc * ROW_F4 + lane] : zero;
        float4 vd = (sd >= 0) ? ob[sd * ROW_F4 + lane] : zero;
        __stcs(&ob[ta * ROW_F4 + lane], va);
        __stcs(&ob[tb * ROW_F4 + lane], vb);
        __stcs(&ob[tc * ROW_F4 + lane], vc);
        __stcs(&ob[td * ROW_F4 + lane], vd);
    }
    for (; i < cnt; i++) {
        int t = (int)s_list[wid][i];
        int s = (int)s_src[wid][i];
        float4 v = (s >= 0) ? ob[s * ROW_F4 + lane] : zero;
        __stcs(&ob[t * ROW_F4 + lane], v);
    }
}

extern "C" void kernel_launch(void* const* d_in, const int* in_sizes, int n_in,
                              void* d_out, int out_size) {
    const float* x = (const float*)d_in[0];
    float* out = (float*)d_out;
    const int B = in_sizes[0] / (L_SEQ * D_FEAT);
    const int ngroups = (B * L_SEQ) >> 2;

    mask_copy_kernel<<<A_GRID, A_THREADS>>>(
        reinterpret_cast<const float4*>(x),
        reinterpret_cast<float4*>(out), ngroups);
    fill_kernel<<<B * B_SLICES, B_THREADS>>>(x, out);
}

// round 15
// speedup vs baseline: 1.0175x; 1.0175x over previous
#include <cuda_runtime.h>
#include <cuda_bf16.h>
#include <math.h>

// ForwardBackwardImputer: out[b,t,:] = x[b, idx_fwd[b,t], :]
// mask[t] = all(|x[b,t,d]| <= 1e-6); idx_fwd = inclusive cummax(mask ? 0 : t).
// (Backward-fill branch of the reference is provably identical to x_fwd;
//  verified rel_err==0 across rounds.)
//
// Kernel A: mask + copy-through + IN-GROUP forward fill (4 rows in registers;
//   missing rows with a valid in-group predecessor are filled for free).
//   Leaves only "unresolved" rows (~2.8%) flagged in g_mask.
// Kernel B: warp-local gather fill of unresolved rows from `out` (resolved
//   rows already hold final values); zero row when no resolved predecessor.

#define L_SEQ 2048
#define D_FEAT 128
#define ROW_F4 (D_FEAT / 4)   // 32 float4 per timestep row
#define ATOL_F 1e-6f

#define A_THREADS 256
#define A_WARPS   8
#define A_GRID    1184        // 148 SMs * 8 (R12-proven config)

#define B_THREADS 256
#define B_WARPS   8
#define B_SLICES  4                      // CTAs per batch row
#define SLICE_LEN (L_SEQ / B_SLICES)     // 512 timesteps per CTA
#define WARP_SPAN 64                     // timesteps per warp in B

// Max problem we support: 1024 batch rows of 2048 steps.
// Byte semantics: 1 = UNRESOLVED after kernel A, 0 = resolved (out is final).
__device__ unsigned char g_mask[1024 * L_SEQ];   // 2 MB

// ---------------- Kernel A: mask + copy-through + in-group fill ------------
__global__ __launch_bounds__(A_THREADS)
void mask_copy_kernel(const float4* __restrict__ x, float4* __restrict__ out,
                      int ngroups) {   // ngroups = (B*L)/4
    const int lane = threadIdx.x & 31;
    const int wid  = threadIdx.x >> 5;
    const unsigned FULL = 0xffffffffu;
    const int totalW = gridDim.x * A_WARPS;

    for (int g = blockIdx.x * A_WARPS + wid; g < ngroups; g += totalW) {
        const int r0 = g << 2;  // flattened (b*L + t) row base
        // Evict-streaming loads: x is read exactly once here.
        float4 v0 = __ldcs(&x[(r0 + 0) * ROW_F4 + lane]);
        float4 v1 = __ldcs(&x[(r0 + 1) * ROW_F4 + lane]);
        float4 v2 = __ldcs(&x[(r0 + 2) * ROW_F4 + lane]);
        float4 v3 = __ldcs(&x[(r0 + 3) * ROW_F4 + lane]);

        bool z0 = (fabsf(v0.x) <= ATOL_F) & (fabsf(v0.y) <= ATOL_F) &
                  (fabsf(v0.z) <= ATOL_F) & (fabsf(v0.w) <= ATOL_F);
        bool z1 = (fabsf(v1.x) <= ATOL_F) & (fabsf(v1.y) <= ATOL_F) &
                  (fabsf(v1.z) <= ATOL_F) & (fabsf(v1.w) <= ATOL_F);
        bool z2 = (fabsf(v2.x) <= ATOL_F) & (fabsf(v2.y) <= ATOL_F) &
                  (fabsf(v2.z) <= ATOL_F) & (fabsf(v2.w) <= ATOL_F);
        bool z3 = (fabsf(v3.x) <= ATOL_F) & (fabsf(v3.y) <= ATOL_F) &
                  (fabsf(v3.z) <= ATOL_F) & (fabsf(v3.w) <= ATOL_F);

        unsigned m0 = __all_sync(FULL, z0);
        unsigned m1 = __all_sync(FULL, z1);
        unsigned m2 = __all_sync(FULL, z2);
        unsigned m3 = __all_sync(FULL, z3);

        // Row 0: its own value if valid, else unresolved.
        if (!m0) __stcs(&out[(r0 + 0) * ROW_F4 + lane], v0);
        // Rows 1-3: own value, else nearest valid in-group predecessor.
        if (!m1)      __stcs(&out[(r0 + 1) * ROW_F4 + lane], v1);
        else if (!m0) __stcs(&out[(r0 + 1) * ROW_F4 + lane], v0);

        if (!m2)      __stcs(&out[(r0 + 2) * ROW_F4 + lane], v2);
        else if (!m1) __stcs(&out[(r0 + 2) * ROW_F4 + lane], v1);
        else if (!m0) __stcs(&out[(r0 + 2) * ROW_F4 + lane], v0);

        if (!m3)      __stcs(&out[(r0 + 3) * ROW_F4 + lane], v3);
        else if (!m2) __stcs(&out[(r0 + 3) * ROW_F4 + lane], v2);
        else if (!m1) __stcs(&out[(r0 + 3) * ROW_F4 + lane], v1);
        else if (!m0) __stcs(&out[(r0 + 3) * ROW_F4 + lane], v0);

        if (lane == 0) {
            // Unresolved = missing AND all-missing group prefix (cumulative AND).
            unsigned u0 = m0;
            unsigned u1 = u0 & m1;
            unsigned u2 = u1 & m2;
            unsigned u3 = u2 & m3;
            uchar4 mm = make_uchar4((unsigned char)u0, (unsigned char)u1,
                                    (unsigned char)u2, (unsigned char)u3);
            *reinterpret_cast<uchar4*>(&g_mask[r0]) = mm;
        }
    }
}

// ---------------- Kernel B: gather fill of unresolved rows -----------------
// grid = B * B_SLICES, 8 warps/CTA, 64 timesteps/warp. g_mask byte==1 means
// unresolved. Source = nearest resolved row (value read from `out`), or the
// zero row when no resolved predecessor exists (sentinel -1, store zeros).
__global__ __launch_bounds__(B_THREADS)
void fill_kernel(const float* __restrict__ x, float* __restrict__ out) {
    const int b     = blockIdx.x >> 2;           // B_SLICES == 4
    const int slice = blockIdx.x & 3;
    float4* __restrict__ ob =
        reinterpret_cast<float4*>(out + (size_t)b * L_SEQ * D_FEAT);

    __shared__ short s_list[B_WARPS][WARP_SPAN];
    __shared__ short s_src [B_WARPS][WARP_SPAN];

    const int lane = threadIdx.x & 31;
    const int wid  = threadIdx.x >> 5;
    const unsigned FULL = 0xffffffffu;
    const unsigned lt = (1u << lane) - 1u;

    const int s0 = slice * SLICE_LEN + wid * WARP_SPAN;   // span start (in row)
    const int gbase = b * L_SEQ;

    // Span mask bytes + speculative carry chunk (overlap the 3 loads).
    unsigned char m0 = g_mask[gbase + s0 + lane];
    unsigned char m1 = g_mask[gbase + s0 + 32 + lane];
    unsigned char mc = (s0 >= 32) ? g_mask[gbase + s0 - 32 + lane]
                                  : (unsigned char)1;

    unsigned miss0 = __ballot_sync(FULL, m0 != 0);
    unsigned miss1 = __ballot_sync(FULL, m1 != 0);
    if ((miss0 | miss1) == 0u) return;          // warp-uniform early exit

    const unsigned res0 = ~miss0;   // resolved within span (out is final)
    const unsigned res1 = ~miss1;

    // Carry-in: nearest resolved index before s0. Sentinel -1 = none ->
    // reference output is the zero row.
    int carry = -1;
    {
        unsigned vb = (s0 >= 32) ? ~__ballot_sync(FULL, mc != 0) : 0u;
        if (vb) {
            carry = (s0 - 32) + (31 - __clz(vb));
        } else {
            for (int off = s0 - 64; off >= 0; off -= 32) {
                unsigned char mb = g_mask[gbase + off + lane];
                unsigned vb2 = ~__ballot_sync(FULL, mb != 0);
                if (vb2) { carry = off + (31 - __clz(vb2)); break; }
            }
        }
    }

    // Per-lane source index for its own timestep (if unresolved).
    unsigned rb0 = res0 & lt;
    int src0 = rb0 ? (s0 + (31 - __clz(rb0))) : carry;

    unsigned rb1 = res1 & lt;
    int src1;
    if (rb1)       src1 = s0 + 32 + (31 - __clz(rb1));
    else if (res0) src1 = s0 + (31 - __clz(res0));
    else           src1 = carry;

    // Ballot-compact (t, src) pairs into smem work lists.
    const int c0  = __popc(miss0);
    const int cnt = c0 + __popc(miss1);
    if (m0) {
        int p = __popc(miss0 & lt);
        s_list[wid][p] = (short)(s0 + lane);
        s_src [wid][p] = (short)src0;
    }
    if (m1) {
        int p = c0 + __popc(miss1 & lt);
        s_list[wid][p] = (short)(s0 + 32 + lane);
        s_src [wid][p] = (short)src1;
    }
    __syncwarp();

    const float4 zero = make_float4(0.f, 0.f, 0.f, 0.f);

    // Fill: gather from OUT (resolved rows hold final values), 4 in flight.
    int i = 0;
    for (; i + 4 <= cnt; i += 4) {
        int ta = (int)s_list[wid][i + 0];
        int tb = (int)s_list[wid][i + 1];
        int tc = (int)s_list[wid][i + 2];
        int td = (int)s_list[wid][i + 3];
        int sa = (int)s_src[wid][i + 0];
        int sb = (int)s_src[wid][i + 1];
        int sc = (int)s_src[wid][i + 2];
        int sd = (int)s_src[wid][i + 3];
        float4 va = (sa >= 0) ? ob[sa * ROW_F4 + lane] : zero;
        float4 vb = (sb >= 0) ? ob[sb * ROW_F4 + lane] : zero;
        float4 vc = (sc >= 0) ? ob[sc * ROW_F4 + lane] : zero;
        float4 vd = (sd >= 0) ? ob[sd * ROW_F4 + lane] : zero;
        __stcs(&ob[ta * ROW_F4 + lane], va);
        __stcs(&ob[tb * ROW_F4 + lane], vb);
        __stcs(&ob[tc * ROW_F4 + lane], vc);
        __stcs(&ob[td * ROW_F4 + lane], vd);
    }
    for (; i < cnt; i++) {
        int t = (int)s_list[wid][i];
        int s = (int)s_src[wid][i];
        float4 v = (s >= 0) ? ob[s * ROW_F4 + lane] : zero;
        __stcs(&ob[t * ROW_F4 + lane], v);
    }
}

extern "C" void kernel_launch(void* const* d_in, const int* in_sizes, int n_in,
                              void* d_out, int out_size) {
    const float* x = (const float*)d_in[0];
    float* out = (float*)d_out;
    const int B = in_sizes[0] / (L_SEQ * D_FEAT);
    const int ngroups = (B * L_SEQ) >> 2;

    mask_copy_kernel<<<A_GRID, A_THREADS>>>(
        reinterpret_cast<const float4*>(x),
        reinterpret_cast<float4*>(out), ngroups);
    fill_kernel<<<B * B_SLICES, B_THREADS>>>(x, out);
}